// round 13
// baseline (speedup 1.0000x reference)
#include <cuda_runtime.h>

// SampleQueryExtractionLayer — FINAL (converged; best measured 7.52us kernel,
// 8.54us dur; 4 consecutive runs within +-0.3us noise band).
// features: [B=4, N=4096(=64x64), C=256] fp32; query_points: [4,8,256,2];
// out: [8192, 256] fp32.
//
// Math: mask = relu(1 - L1(p, grid) + eps)^2 normalized over the 64x64 grid
// is supported on the 4 corners of the containing unit cell (all other
// lattice points contribute <= eps^2 = 1e-8); the dense einsum collapses to
// a 4-tap weighted gather. Measured rel_err 6.3e-8 (budget 1e-3).
//
// Structure (best of 7 tested designs):
//  - single wave: 4096 CTAs x 64 threads, exactly 32 regs = full RF at
//    64 warps/SM; max TLP (all ILP variants regressed: regs > 32 cut residency)
//  - each CTA: queries g and g+4096 sequentially (gather data regs reused;
//    traffic from batches 0-1 / 2-3 interleaves across both L2 dies)
//  - both qp loads issue at t=0 -> one dependent load hop per thread
//  - weight math (incl. MUFU.RCP via __fdividef) strictly off the address
//    path, fully overlapped with the 4 front-batched independent gathers
//  - evict-first (__stcs) output stores keep the 16MB feature matrix
//    L2-resident across graph replays
//
// Falsified alternatives (measured): 2-tap sparsity (traffic/2 -> no gain;
// not BW-bound), f32x2 packed epilogue (-20% instr -> +0.6us), cp.async.bulk
// pipeline (+2us), batched ILP=2 (+1.6us), adjacent-pair qp packing (+0.4us).
// Residual runtime = fixed launch/CTA-distribution overhead (~5000 cyc) at
// DVFS-floor clocks + one exposed qp->gather chain; remaining edits are all
// below measurement noise.

#define EPS_F 0.0001f

__device__ __forceinline__ void do_query(const float* __restrict__ feat,
                                         float* __restrict__ out,
                                         float2 p, int g, int c4)
{
    const int y0 = __float2int_rd(p.x);
    const int x0 = __float2int_rd(p.y);
    const int b  = g >> 11;                      // 2048 queries per batch

    const float4* r00 = (const float4*)feat
                        + (size_t)(b * 4096 + y0 * 64 + x0) * 64 + c4;
    // 4 independent gathers, front-batched.
    const float4 f00 = __ldg(r00);
    const float4 f01 = __ldg(r00 + 64);          // (y0, x0+1)
    const float4 f10 = __ldg(r00 + 64 * 64);     // (y0+1, x0)
    const float4 f11 = __ldg(r00 + 64 * 65);     // (y0+1, x0+1)

    // Weight math overlaps the gather latency.
    const float dy = p.x - (float)y0;
    const float dx = p.y - (float)x0;
    const float m00 = fmaxf(0.f, 1.f - (dy + dx)       + EPS_F);
    const float m01 = fmaxf(0.f, 1.f - (dy + 1.f - dx) + EPS_F);
    const float m10 = fmaxf(0.f, 1.f - (1.f - dy + dx) + EPS_F);
    const float m11 = fmaxf(0.f, 1.f - (2.f - dy - dx) + EPS_F);
    const float w00 = m00 * m00;
    const float w01 = m01 * m01;
    const float w10 = m10 * m10;
    const float w11 = m11 * m11;
    const float inv = __fdividef(1.f, w00 + w01 + w10 + w11 + EPS_F);

    float4 acc;
    acc.x = (w00*f00.x + w01*f01.x + w10*f10.x + w11*f11.x) * inv;
    acc.y = (w00*f00.y + w01*f01.y + w10*f10.y + w11*f11.y) * inv;
    acc.z = (w00*f00.z + w01*f01.z + w10*f10.z + w11*f11.z) * inv;
    acc.w = (w00*f00.w + w01*f01.w + w10*f10.w + w11*f11.w) * inv;

    // Evict-first store: keep the feature matrix resident in L2.
    __stcs(((float4*)out) + (size_t)g * 64 + c4, acc);
}

__global__ __launch_bounds__(64)
void sqe_kernel(const float* __restrict__ feat,
                const float* __restrict__ qp,
                float* __restrict__ out)
{
    const int c4  = threadIdx.x;                 // 0..63, float4 lane in C
    const int grp = blockIdx.x;                  // 0..4095

    const int q0 = grp;                          // batches 0-1
    const int q1 = grp + 4096;                   // batches 2-3

    // Both qp loads in flight immediately (broadcast within the block).
    const float2 p0 = __ldg(((const float2*)qp) + q0);
    const float2 p1 = __ldg(((const float2*)qp) + q1);

    do_query(feat, out, p0, q0, c4);
    do_query(feat, out, p1, q1, c4);
}

extern "C" void kernel_launch(void* const* d_in, const int* in_sizes, int n_in,
                              void* d_out, int out_size)
{
    (void)in_sizes; (void)n_in; (void)out_size;
    const float* feat = (const float*)d_in[0];
    const float* qp   = (const float*)d_in[1];
    float* out        = (float*)d_out;

    // 4096 groups x 2 sequential queries = 8192 queries, single wave.
    sqe_kernel<<<4096, 64>>>(feat, qp, out);
}

// round 14
// speedup vs baseline: 1.0296x; 1.0296x over previous
#include <cuda_runtime.h>

// SampleQueryExtractionLayer — FINAL (converged; best measured 7.52us kernel
// / 8.54us dur; 5 consecutive runs of this structure within +-0.3us noise).
// features: [B=4, N=4096(=64x64), C=256] fp32; query_points: [4,8,256,2];
// out: [8192, 256] fp32.
//
// Math: mask = relu(1 - L1(p, grid) + eps)^2 normalized over the 64x64 grid
// is supported on the 4 corners of the containing unit cell (all other
// lattice points contribute <= eps^2 = 1e-8); the dense einsum collapses to
// a 4-tap weighted gather. Measured rel_err 6.3e-8 (budget 1e-3).
//
// Structure (best of 7 tested designs):
//  - single wave: 4096 CTAs x 64 threads, exactly 32 regs = full RF at
//    64 warps/SM; max TLP (all ILP variants regressed: regs > 32 cut residency)
//  - each CTA: queries g and g+4096 sequentially (gather data regs reused;
//    traffic from batches 0-1 / 2-3 interleaves across both L2 dies)
//  - both qp loads issue at t=0 -> one dependent load hop per thread
//  - weight math (incl. MUFU.RCP via __fdividef) strictly off the address
//    path, fully overlapped with the 4 front-batched independent gathers
//  - evict-first (__stcs) output stores keep the 16MB feature matrix
//    L2-resident across graph replays
//
// Falsified alternatives (measured): 2-tap sparsity (traffic/2 -> no gain;
// not BW-bound), f32x2 packed epilogue (-20% instr -> +0.6us), cp.async.bulk
// pipeline (+2us), batched ILP=2 (+1.6us), adjacent-pair qp packing (+0.4us),
// chain hoisting / CTA-size permutations (neutral). Residual runtime = fixed
// launch/CTA-distribution overhead at replay clocks + one exposed qp->gather
// chain; all remaining edits are below measurement noise.

#define EPS_F 0.0001f

__device__ __forceinline__ void do_query(const float* __restrict__ feat,
                                         float* __restrict__ out,
                                         float2 p, int g, int c4)
{
    const int y0 = __float2int_rd(p.x);
    const int x0 = __float2int_rd(p.y);
    const int b  = g >> 11;                      // 2048 queries per batch

    const float4* r00 = (const float4*)feat
                        + (size_t)(b * 4096 + y0 * 64 + x0) * 64 + c4;
    // 4 independent gathers, front-batched.
    const float4 f00 = __ldg(r00);
    const float4 f01 = __ldg(r00 + 64);          // (y0, x0+1)
    const float4 f10 = __ldg(r00 + 64 * 64);     // (y0+1, x0)
    const float4 f11 = __ldg(r00 + 64 * 65);     // (y0+1, x0+1)

    // Weight math overlaps the gather latency.
    const float dy = p.x - (float)y0;
    const float dx = p.y - (float)x0;
    const float m00 = fmaxf(0.f, 1.f - (dy + dx)       + EPS_F);
    const float m01 = fmaxf(0.f, 1.f - (dy + 1.f - dx) + EPS_F);
    const float m10 = fmaxf(0.f, 1.f - (1.f - dy + dx) + EPS_F);
    const float m11 = fmaxf(0.f, 1.f - (2.f - dy - dx) + EPS_F);
    const float w00 = m00 * m00;
    const float w01 = m01 * m01;
    const float w10 = m10 * m10;
    const float w11 = m11 * m11;
    const float inv = __fdividef(1.f, w00 + w01 + w10 + w11 + EPS_F);

    float4 acc;
    acc.x = (w00*f00.x + w01*f01.x + w10*f10.x + w11*f11.x) * inv;
    acc.y = (w00*f00.y + w01*f01.y + w10*f10.y + w11*f11.y) * inv;
    acc.z = (w00*f00.z + w01*f01.z + w10*f10.z + w11*f11.z) * inv;
    acc.w = (w00*f00.w + w01*f01.w + w10*f10.w + w11*f11.w) * inv;

    // Evict-first store: keep the feature matrix resident in L2.
    __stcs(((float4*)out) + (size_t)g * 64 + c4, acc);
}

__global__ __launch_bounds__(64)
void sqe_kernel(const float* __restrict__ feat,
                const float* __restrict__ qp,
                float* __restrict__ out)
{
    const int c4  = threadIdx.x;                 // 0..63, float4 lane in C
    const int grp = blockIdx.x;                  // 0..4095

    const int q0 = grp;                          // batches 0-1
    const int q1 = grp + 4096;                   // batches 2-3

    // Both qp loads in flight immediately (broadcast within the block).
    const float2 p0 = __ldg(((const float2*)qp) + q0);
    const float2 p1 = __ldg(((const float2*)qp) + q1);

    do_query(feat, out, p0, q0, c4);
    do_query(feat, out, p1, q1, c4);
}

extern "C" void kernel_launch(void* const* d_in, const int* in_sizes, int n_in,
                              void* d_out, int out_size)
{
    (void)in_sizes; (void)n_in; (void)out_size;
    const float* feat = (const float*)d_in[0];
    const float* qp   = (const float*)d_in[1];
    float* out        = (float*)d_out;

    // 4096 groups x 2 sequential queries = 8192 queries, single wave.
    sqe_kernel<<<4096, 64>>>(feat, qp, out);
}